// round 2
// baseline (speedup 1.0000x reference)
#include <cuda_runtime.h>
#include <cuda_bf16.h>

// GRU: B=256, T=2000, I=23, H=128. One CTA per batch element; 384 threads,
// thread r owns gate-row r (r<128: reset, 128..255: update, 256..383: candidate).
// W_hh row (128 f32) register-resident; h broadcast from shared; W_ih in shared.

#define BB 256
#define TT 2000
#define II 23
#define HH 128
#define G3 384

__device__ __forceinline__ float sigmoidf_(float v) {
    return 1.0f / (1.0f + __expf(-v));
}

__global__ __launch_bounds__(G3, 1) void gru_kernel(
    const float* __restrict__ x,     // [B, T, I]
    const float* __restrict__ Wih,   // [3H, I]
    const float* __restrict__ Whh,   // [3H, H]
    const float* __restrict__ bih,   // [3H]
    const float* __restrict__ bhh,   // [3H]
    float* __restrict__ out)         // [B, H]
{
    const int b = blockIdx.x;
    const int r = threadIdx.x;

    __shared__ __align__(16) float h_sh[HH];
    __shared__ float rg[HH];
    __shared__ float zg[HH];
    __shared__ float gxn[HH];
    __shared__ float ghn[HH];
    __shared__ float x_sh[2][II + 1];
    __shared__ float Wih_sh[G3 * II];   // 35.3 KB; (r*23+k)%32 conflict-free

    // Cooperative load of W_ih into shared
    for (int i = r; i < G3 * II; i += G3) Wih_sh[i] = Wih[i];

    // Register-resident W_hh row for this thread
    float w[HH];
    {
        const float4* src = reinterpret_cast<const float4*>(Whh + r * HH);
#pragma unroll
        for (int k = 0; k < HH / 4; k++) {
            float4 v = src[k];
            w[4 * k + 0] = v.x;
            w[4 * k + 1] = v.y;
            w[4 * k + 2] = v.z;
            w[4 * k + 3] = v.w;
        }
    }
    const float my_bih = bih[r];
    const float my_bhh = bhh[r];

    if (r < HH) h_sh[r] = 0.0f;

    const float* xb = x + (size_t)b * TT * II;
    if (r < II) x_sh[0][r] = xb[r];          // x[t=0]

    float hsum = 0.0f;
    __syncthreads();

    for (int t = 0; t < TT; t++) {
        const int cur = t & 1;
        const int nxt = cur ^ 1;

        // Prefetch x[t+1] early so the LDG latency hides behind the dot product.
        // IMPORTANT: the SAME threads (256..256+II-1) that will store into
        // x_sh[nxt] must do the load.
        float xpre = 0.0f;
        if (r >= 2 * HH && r < 2 * HH + II && (t + 1) < TT)
            xpre = xb[(t + 1) * II + (r - 2 * HH)];

        // gh_r = dot(W_hh[r,:], h) + b_hh[r]   (broadcast LDS.128 of h)
        float gh = 0.0f;
#pragma unroll
        for (int k = 0; k < HH; k += 4) {
            float4 hv = *reinterpret_cast<const float4*>(&h_sh[k]);
            gh = fmaf(w[k + 0], hv.x, gh);
            gh = fmaf(w[k + 1], hv.y, gh);
            gh = fmaf(w[k + 2], hv.z, gh);
            gh = fmaf(w[k + 3], hv.w, gh);
        }
        gh += my_bhh;

        // gx_r = dot(W_ih[r,:], x[b,t,:]) + b_ih[r]
        float gx = my_bih;
#pragma unroll
        for (int k = 0; k < II; k++) {
            gx = fmaf(Wih_sh[r * II + k], x_sh[cur][k], gx);
        }

        if (r < HH) {
            rg[r] = sigmoidf_(gx + gh);
        } else if (r < 2 * HH) {
            zg[r - HH] = sigmoidf_(gx + gh);
        } else {
            gxn[r - 2 * HH] = gx;
            ghn[r - 2 * HH] = gh;
        }
        __syncthreads();

        if (r < HH) {
            float n = tanhf(fmaf(rg[r], ghn[r], gxn[r]));
            float z = zg[r];
            float h_old = h_sh[r];
            float h_new = fmaf(z, h_old - n, n);   // (1-z)*n + z*h
            h_sh[r] = h_new;
            hsum += h_new;
        } else if (r >= 2 * HH && r < 2 * HH + II) {
            x_sh[nxt][r - 2 * HH] = xpre;          // stage next-step input
        }
        __syncthreads();
    }

    if (r < HH) {
        out[b * HH + r] = hsum * (1.0f / (float)TT);
    }
}

extern "C" void kernel_launch(void* const* d_in, const int* in_sizes, int n_in,
                              void* d_out, int out_size) {
    const float* x    = (const float*)d_in[0];
    const float* Wih  = (const float*)d_in[1];
    const float* Whh  = (const float*)d_in[2];
    const float* bih  = (const float*)d_in[3];
    const float* bhh  = (const float*)d_in[4];
    float* out = (float*)d_out;
    (void)in_sizes; (void)n_in; (void)out_size;

    gru_kernel<<<BB, G3>>>(x, Wih, Whh, bih, bhh, out);
}

// round 3
// speedup vs baseline: 1.2762x; 1.2762x over previous
#include <cuda_runtime.h>
#include <cuda_bf16.h>

#define BB 256
#define TT 2000
#define II 23
#define HH 128
#define G3 384
#define TCH 100
#define NCH (TT / TCH)   // 20 chunks

// Scratch: gx[t][b][r] = W_ih[r,:].x[b,t,:] + b_ih[r]  (786 MB, sanctioned __device__ scratch)
__device__ float g_gx[(size_t)TT * BB * G3];

// ---- packed f32x2 helpers (FFMA2 only reachable via PTX) ----
__device__ __forceinline__ unsigned long long fma2(unsigned long long a,
                                                   unsigned long long b,
                                                   unsigned long long c) {
    unsigned long long d;
    asm("fma.rn.f32x2 %0, %1, %2, %3;" : "=l"(d) : "l"(a), "l"(b), "l"(c));
    return d;
}
__device__ __forceinline__ unsigned long long add2(unsigned long long a,
                                                   unsigned long long b) {
    unsigned long long d;
    asm("add.rn.f32x2 %0, %1, %2;" : "=l"(d) : "l"(a), "l"(b));
    return d;
}
__device__ __forceinline__ unsigned long long pack2(float lo, float hi) {
    unsigned long long d;
    asm("mov.b64 %0, {%1, %2};" : "=l"(d) : "f"(lo), "f"(hi));
    return d;
}
__device__ __forceinline__ void unpack2(unsigned long long v, float& lo, float& hi) {
    asm("mov.b64 {%0, %1}, %2;" : "=f"(lo), "=f"(hi) : "l"(v));
}

__device__ __forceinline__ float sigmoidf_(float v) {
    return __fdividef(1.0f, 1.0f + __expf(-v));
}
__device__ __forceinline__ float tanhf_(float a) {
    float e = __expf(-2.0f * a);
    return __fdividef(1.0f - e, 1.0f + e);
}

// ============================================================
// Phase 1: gx[t][b][r] for all t. grid (NCH, BB), block 384.
// t-vectorized: each thread computes its row r for 4 timesteps
// at once using f32x2 (W broadcast-packed, x pairs from shared).
// ============================================================
__global__ __launch_bounds__(G3) void gx_kernel(
    const float* __restrict__ x,     // [B, T, I]
    const float* __restrict__ Wih,   // [3H, I]
    const float* __restrict__ bih)   // [3H]
{
    const int b   = blockIdx.y;
    const int t0g = blockIdx.x * TCH;
    const int r   = threadIdx.x;

    __shared__ __align__(16) float xt[II][TCH + 8];  // transposed chunk, stride 108

    // Load x[b, t0g:t0g+TCH, :] transposed into shared
    const float* xbase = x + ((size_t)b * TT + t0g) * II;
    for (int e = r; e < TCH * II; e += G3) {
        int t = e / II;
        int k = e - t * II;
        xt[k][t] = xbase[e];
    }

    // W_ih row r, broadcast-packed; bias pair
    unsigned long long ww[II];
#pragma unroll
    for (int k = 0; k < II; k++) {
        float wv = Wih[r * II + k];
        ww[k] = pack2(wv, wv);
    }
    const float bv = bih[r];
    const unsigned long long bp = pack2(bv, bv);

    __syncthreads();

    for (int t0 = 0; t0 < TCH; t0 += 4) {
        unsigned long long a01 = bp, a23 = bp;
#pragma unroll
        for (int k = 0; k < II; k++) {
            ulonglong2 xv = *reinterpret_cast<const ulonglong2*>(&xt[k][t0]);
            a01 = fma2(ww[k], xv.x, a01);
            a23 = fma2(ww[k], xv.y, a23);
        }
        float g0, g1, g2, g3;
        unpack2(a01, g0, g1);
        unpack2(a23, g2, g3);
        size_t o = ((size_t)(t0g + t0) * BB + b) * G3 + r;
        const size_t stp = (size_t)BB * G3;
        g_gx[o]           = g0;
        g_gx[o + stp]     = g1;
        g_gx[o + 2 * stp] = g2;
        g_gx[o + 3 * stp] = g3;
    }
}

// ============================================================
// Phase 2: recurrence. grid 128 (single wave), block 384.
// Each CTA runs TWO batch elements (b0, b1) in lockstep:
// 2 independent dot chains per thread -> ILP + amortized barriers.
// ============================================================
__global__ __launch_bounds__(G3, 1) void gru_rec(
    const float* __restrict__ Whh,   // [3H, H]
    const float* __restrict__ bhh,   // [3H]
    float* __restrict__ out)         // [B, H]
{
    const int b0 = blockIdx.x * 2;
    const int b1 = b0 + 1;
    const int r  = threadIdx.x;

    __shared__ __align__(16) float h_sh[2][HH];
    __shared__ float rg[2][HH], zg[2][HH], gxn[2][HH], ghn[2][HH];

    // W_hh row r, packed f32x2 (64 u64 = 128 f32 regs)
    unsigned long long wp[HH / 2];
    {
        const float4* src = reinterpret_cast<const float4*>(Whh + r * HH);
#pragma unroll
        for (int j = 0; j < HH / 4; j++) {
            float4 v = src[j];
            wp[2 * j]     = pack2(v.x, v.y);
            wp[2 * j + 1] = pack2(v.z, v.w);
        }
    }
    const float my_bhh = bhh[r];

    if (r < HH) { h_sh[0][r] = 0.0f; h_sh[1][r] = 0.0f; }

    const float* gx0p = g_gx + (size_t)b0 * G3 + r;   // + t*BB*G3
    const float* gx1p = g_gx + (size_t)b1 * G3 + r;
    const size_t stp = (size_t)BB * G3;

    float gx0 = gx0p[0];
    float gx1 = gx1p[0];
    float hsum0 = 0.0f, hsum1 = 0.0f;
    __syncthreads();

    for (int t = 0; t < TT; t++) {
        // Prefetch next step's gx (hides DRAM latency behind the dot)
        float gx0n = 0.0f, gx1n = 0.0f;
        if (t + 1 < TT) {
            gx0n = gx0p[(size_t)(t + 1) * stp];
            gx1n = gx1p[(size_t)(t + 1) * stp];
        }

        // gh = dot(W_hh[r,:], h) for both batches; 4 independent f32x2 chains
        unsigned long long a0a = 0ull, a0b = 0ull, a1a = 0ull, a1b = 0ull;
        const ulonglong2* h0p = reinterpret_cast<const ulonglong2*>(h_sh[0]);
        const ulonglong2* h1p = reinterpret_cast<const ulonglong2*>(h_sh[1]);
#pragma unroll
        for (int j = 0; j < HH / 4; j++) {
            ulonglong2 hv0 = h0p[j];
            a0a = fma2(wp[2 * j],     hv0.x, a0a);
            a0b = fma2(wp[2 * j + 1], hv0.y, a0b);
            ulonglong2 hv1 = h1p[j];
            a1a = fma2(wp[2 * j],     hv1.x, a1a);
            a1b = fma2(wp[2 * j + 1], hv1.y, a1b);
        }
        float s0lo, s0hi, s1lo, s1hi;
        unpack2(add2(a0a, a0b), s0lo, s0hi);
        unpack2(add2(a1a, a1b), s1lo, s1hi);
        float gh0 = s0lo + s0hi + my_bhh;
        float gh1 = s1lo + s1hi + my_bhh;

        if (r < HH) {
            rg[0][r] = sigmoidf_(gx0 + gh0);
            rg[1][r] = sigmoidf_(gx1 + gh1);
        } else if (r < 2 * HH) {
            zg[0][r - HH] = sigmoidf_(gx0 + gh0);
            zg[1][r - HH] = sigmoidf_(gx1 + gh1);
        } else {
            gxn[0][r - 2 * HH] = gx0;  ghn[0][r - 2 * HH] = gh0;
            gxn[1][r - 2 * HH] = gx1;  ghn[1][r - 2 * HH] = gh1;
        }
        __syncthreads();

        if (r < HH) {
            float n0 = tanhf_(fmaf(rg[0][r], ghn[0][r], gxn[0][r]));
            float z0 = zg[0][r];
            float h0 = fmaf(z0, h_sh[0][r] - n0, n0);   // (1-z)n + zh
            h_sh[0][r] = h0;  hsum0 += h0;

            float n1 = tanhf_(fmaf(rg[1][r], ghn[1][r], gxn[1][r]));
            float z1 = zg[1][r];
            float h1 = fmaf(z1, h_sh[1][r] - n1, n1);
            h_sh[1][r] = h1;  hsum1 += h1;
        }
        __syncthreads();

        gx0 = gx0n;
        gx1 = gx1n;
    }

    if (r < HH) {
        out[b0 * HH + r] = hsum0 * (1.0f / (float)TT);
        out[b1 * HH + r] = hsum1 * (1.0f / (float)TT);
    }
}

extern "C" void kernel_launch(void* const* d_in, const int* in_sizes, int n_in,
                              void* d_out, int out_size) {
    const float* x   = (const float*)d_in[0];
    const float* Wih = (const float*)d_in[1];
    const float* Whh = (const float*)d_in[2];
    const float* bih = (const float*)d_in[3];
    const float* bhh = (const float*)d_in[4];
    float* out = (float*)d_out;
    (void)in_sizes; (void)n_in; (void)out_size;

    gx_kernel<<<dim3(NCH, BB), G3>>>(x, Wih, bih);
    gru_rec<<<BB / 2, G3>>>(Whh, bhh, out);
}

// round 4
// speedup vs baseline: 1.3320x; 1.0438x over previous
#include <cuda_runtime.h>
#include <cuda_bf16.h>

#define BB 256
#define TT 2000
#define II 23
#define HH 128
#define G3 384
#define TCH 100
#define NCH (TT / TCH)   // 20 chunks

// Scratch: gx[t][b][r] = W_ih[r,:].x[b,t,:] + b_ih[r]  (786 MB __device__ scratch)
__device__ float g_gx[(size_t)TT * BB * G3];

// ---- packed f32x2 helpers ----
__device__ __forceinline__ unsigned long long fma2(unsigned long long a,
                                                   unsigned long long b,
                                                   unsigned long long c) {
    unsigned long long d;
    asm("fma.rn.f32x2 %0, %1, %2, %3;" : "=l"(d) : "l"(a), "l"(b), "l"(c));
    return d;
}
__device__ __forceinline__ unsigned long long add2(unsigned long long a,
                                                   unsigned long long b) {
    unsigned long long d;
    asm("add.rn.f32x2 %0, %1, %2;" : "=l"(d) : "l"(a), "l"(b));
    return d;
}
__device__ __forceinline__ unsigned long long pack2(float lo, float hi) {
    unsigned long long d;
    asm("mov.b64 %0, {%1, %2};" : "=l"(d) : "f"(lo), "f"(hi));
    return d;
}
__device__ __forceinline__ void unpack2(unsigned long long v, float& lo, float& hi) {
    asm("mov.b64 {%0, %1}, %2;" : "=f"(lo), "=f"(hi) : "l"(v));
}

// MUFU.TANH — single-op tanh on sm_75+
__device__ __forceinline__ float tanh_ap(float x) {
    float y;
    asm("tanh.approx.f32 %0, %1;" : "=f"(y) : "f"(x));
    return y;
}
// sigmoid(x) = 0.5*tanh(0.5x) + 0.5  (1 MUFU + 2 FMA)
__device__ __forceinline__ float sigmoid_ap(float x) {
    return fmaf(tanh_ap(0.5f * x), 0.5f, 0.5f);
}

// ============================================================
// Phase 1: gx[t][b][r]. grid (NCH, BB), block 384.
// ============================================================
__global__ __launch_bounds__(G3) void gx_kernel(
    const float* __restrict__ x,     // [B, T, I]
    const float* __restrict__ Wih,   // [3H, I]
    const float* __restrict__ bih)   // [3H]
{
    const int b   = blockIdx.y;
    const int t0g = blockIdx.x * TCH;
    const int r   = threadIdx.x;

    __shared__ __align__(16) float xt[II][TCH + 8];

    const float* xbase = x + ((size_t)b * TT + t0g) * II;
    for (int e = r; e < TCH * II; e += G3) {
        int t = e / II;
        int k = e - t * II;
        xt[k][t] = xbase[e];
    }

    unsigned long long ww[II];
#pragma unroll
    for (int k = 0; k < II; k++) {
        float wv = Wih[r * II + k];
        ww[k] = pack2(wv, wv);
    }
    const float bv = bih[r];
    const unsigned long long bp = pack2(bv, bv);

    __syncthreads();

    for (int t0 = 0; t0 < TCH; t0 += 4) {
        unsigned long long a01 = bp, a23 = bp;
#pragma unroll
        for (int k = 0; k < II; k++) {
            ulonglong2 xv = *reinterpret_cast<const ulonglong2*>(&xt[k][t0]);
            a01 = fma2(ww[k], xv.x, a01);
            a23 = fma2(ww[k], xv.y, a23);
        }
        float g0, g1, g2, g3;
        unpack2(a01, g0, g1);
        unpack2(a23, g2, g3);
        size_t o = ((size_t)(t0g + t0) * BB + b) * G3 + r;
        const size_t stp = (size_t)BB * G3;
        g_gx[o]           = g0;
        g_gx[o + stp]     = g1;
        g_gx[o + 2 * stp] = g2;
        g_gx[o + 3 * stp] = g3;
    }
}

// ============================================================
// Phase 2: recurrence. grid 128 (single wave), block 384,
// 2 batch elements per CTA. MUFU.TANH gates; phase-2 tail
// split across 256 threads (128 per batch).
// ============================================================
__global__ __launch_bounds__(G3, 1) void gru_rec(
    const float* __restrict__ Whh,   // [3H, H]
    const float* __restrict__ bhh,   // [3H]
    float* __restrict__ out)         // [B, H]
{
    const int b0 = blockIdx.x * 2;
    const int b1 = b0 + 1;
    const int r  = threadIdx.x;

    __shared__ __align__(16) float h_sh[2][HH];
    __shared__ __align__(8) float2 rg2[HH];   // (batch0, batch1)
    __shared__ __align__(8) float2 zg2[HH];
    __shared__ __align__(8) float2 gxn2[HH];
    __shared__ __align__(8) float2 ghn2[HH];

    // W_hh row r packed f32x2
    unsigned long long wp[HH / 2];
    {
        const float4* src = reinterpret_cast<const float4*>(Whh + r * HH);
#pragma unroll
        for (int j = 0; j < HH / 4; j++) {
            float4 v = src[j];
            wp[2 * j]     = pack2(v.x, v.y);
            wp[2 * j + 1] = pack2(v.z, v.w);
        }
    }
    const float my_bhh = bhh[r];

    if (r < HH) { h_sh[0][r] = 0.0f; h_sh[1][r] = 0.0f; }

    const float* gx0p = g_gx + (size_t)b0 * G3 + r;   // + t*BB*G3
    const float* gx1p = g_gx + (size_t)b1 * G3 + r;
    const size_t stp = (size_t)BB * G3;

    float gx0 = gx0p[0];
    float gx1 = gx1p[0];
    float hsum = 0.0f;                 // batch0 on tid<128, batch1 on tid 128..255
    __syncthreads();

    for (int t = 0; t < TT; t++) {
        // prefetch next gx
        float gx0n = 0.0f, gx1n = 0.0f;
        if (t + 1 < TT) {
            gx0n = gx0p[(size_t)(t + 1) * stp];
            gx1n = gx1p[(size_t)(t + 1) * stp];
        }

        // gh = W_hh[r,:] . h  for both batches — 4 independent f32x2 chains
        unsigned long long a0a = 0ull, a0b = 0ull, a1a = 0ull, a1b = 0ull;
        const ulonglong2* h0p = reinterpret_cast<const ulonglong2*>(h_sh[0]);
        const ulonglong2* h1p = reinterpret_cast<const ulonglong2*>(h_sh[1]);
#pragma unroll
        for (int j = 0; j < HH / 4; j++) {
            ulonglong2 hv0 = h0p[j];
            a0a = fma2(wp[2 * j],     hv0.x, a0a);
            a0b = fma2(wp[2 * j + 1], hv0.y, a0b);
            ulonglong2 hv1 = h1p[j];
            a1a = fma2(wp[2 * j],     hv1.x, a1a);
            a1b = fma2(wp[2 * j + 1], hv1.y, a1b);
        }
        float s0lo, s0hi, s1lo, s1hi;
        unpack2(add2(a0a, a0b), s0lo, s0hi);
        unpack2(add2(a1a, a1b), s1lo, s1hi);
        float gh0 = s0lo + s0hi + my_bhh;
        float gh1 = s1lo + s1hi + my_bhh;

        if (r < HH) {
            rg2[r] = make_float2(sigmoid_ap(gx0 + gh0), sigmoid_ap(gx1 + gh1));
        } else if (r < 2 * HH) {
            zg2[r - HH] = make_float2(sigmoid_ap(gx0 + gh0), sigmoid_ap(gx1 + gh1));
        } else {
            gxn2[r - 2 * HH] = make_float2(gx0, gx1);
            ghn2[r - 2 * HH] = make_float2(gh0, gh1);
        }
        __syncthreads();

        // phase 2: batch0 -> threads 0..127, batch1 -> threads 128..255
        if (r < HH) {
            const int e = r;
            float n  = tanh_ap(fmaf(rg2[e].x, ghn2[e].x, gxn2[e].x));
            float z  = zg2[e].x;
            float hn = fmaf(z, h_sh[0][e] - n, n);
            h_sh[0][e] = hn;
            hsum += hn;
        } else if (r < 2 * HH) {
            const int e = r - HH;
            float n  = tanh_ap(fmaf(rg2[e].y, ghn2[e].y, gxn2[e].y));
            float z  = zg2[e].y;
            float hn = fmaf(z, h_sh[1][e] - n, n);
            h_sh[1][e] = hn;
            hsum += hn;
        }
        __syncthreads();

        gx0 = gx0n;
        gx1 = gx1n;
    }

    if (r < HH) {
        out[b0 * HH + r] = hsum * (1.0f / (float)TT);
    } else if (r < 2 * HH) {
        out[b1 * HH + (r - HH)] = hsum * (1.0f / (float)TT);
    }
}

extern "C" void kernel_launch(void* const* d_in, const int* in_sizes, int n_in,
                              void* d_out, int out_size) {
    const float* x   = (const float*)d_in[0];
    const float* Wih = (const float*)d_in[1];
    const float* Whh = (const float*)d_in[2];
    const float* bih = (const float*)d_in[3];
    const float* bhh = (const float*)d_in[4];
    float* out = (float*)d_out;
    (void)in_sizes; (void)n_in; (void)out_size;

    gx_kernel<<<dim3(NCH, BB), G3>>>(x, Wih, bih);
    gru_rec<<<BB / 2, G3>>>(Whh, bhh, out);
}